// round 16
// baseline (speedup 1.0000x reference)
#include <cuda_runtime.h>
#include <cuda_fp16.h>
#include <cstdint>

// Problem dims (fixed by the reference)
#define BB 2
#define TT 2048
#define DD 1024
#define NN 16
#define DCONV 4
#define MROWS (BB*TT)          // 4096
#define E2 (2*DD)              // 2048
#define NPAR (2*NN+1)          // 33
#define NPAD 64                // padded x_proj output dim
#define NCH 32                 // scan chunks
#define CHL (TT/NCH)           // 64 steps per chunk
#define KSPL 4                 // x_proj K-split factor
#define KCH (DD/KSPL)          // 256

// ---------- scratch (static device allocations only) ----------
__device__ float g_xz[(size_t)MROWS * E2];        // in_proj output (x_in | z)
__device__ float g_params[(size_t)KSPL * MROWS * NPAR];  // x_proj partials
__device__ __half g_xh [(size_t)MROWS * DD];      // x in fp16
__device__ __half g_w1hi[(size_t)E2 * DD], g_w1lo[(size_t)E2 * DD];
__device__ __half g_w2hi[(size_t)DD * DD], g_w2lo[(size_t)DD * DD];
__device__ __half g_xchi[(size_t)MROWS * DD], g_xclo[(size_t)MROWS * DD]; // xconv hi/lo
__device__ __half g_wxhi[(size_t)NPAD * DD], g_wxlo[(size_t)NPAD * DD];   // padded x_proj_w hi/lo
__device__ __half g_yh [(size_t)MROWS * DD];      // scan output in fp16
__device__ float g_P   [(size_t)BB * NCH * NN * DD];
__device__ float g_hend[(size_t)BB * NCH * NN * DD];

// =====================================================================
// Merged precision prep:
//  range0: x -> fp16           range1: w1 -> fp16 hi/lo
//  range2: w2 -> fp16 hi/lo    range3: x_proj_w -> padded fp16 hi/lo
// =====================================================================
#define N_X4   (MROWS*DD/4)
#define N_W14  (E2*DD/4)
#define N_W24  (DD*DD/4)
#define N_WX4  (NPAD*DD/4)          // padded slots
#define N_WXR  (NPAR*DD/4)          // real x_proj_w float4 count (8448)
#define N_PREP (N_X4 + N_W14 + N_W24 + N_WX4)

__device__ __forceinline__ void split_one(float4 v, __half* hi, __half* lo, int i) {
    __half hx = __float2half_rn(v.x);
    __half hy = __float2half_rn(v.y);
    __half hz = __float2half_rn(v.z);
    __half hw = __float2half_rn(v.w);
    __half2 h01; h01.x = hx; h01.y = hy;
    __half2 h23; h23.x = hz; h23.y = hw;
    ((__half2*)hi)[i*2]   = h01;
    ((__half2*)hi)[i*2+1] = h23;
    __half2 l01, l23;
    l01.x = __float2half_rn(v.x - __half2float(hx));
    l01.y = __float2half_rn(v.y - __half2float(hy));
    l23.x = __float2half_rn(v.z - __half2float(hz));
    l23.y = __float2half_rn(v.w - __half2float(hw));
    ((__half2*)lo)[i*2]   = l01;
    ((__half2*)lo)[i*2+1] = l23;
}

__global__ void prep_kernel(const float* __restrict__ x,
                            const float* __restrict__ w1,
                            const float* __restrict__ w2,
                            const float* __restrict__ wx,
                            __half* __restrict__ xh,
                            __half* __restrict__ w1hi, __half* __restrict__ w1lo,
                            __half* __restrict__ w2hi, __half* __restrict__ w2lo,
                            __half* __restrict__ wxhi, __half* __restrict__ wxlo)
{
    int i = blockIdx.x * blockDim.x + threadIdx.x;
    if (i < N_X4) {
        float4 v = ((const float4*)x)[i];
        ((__half2*)xh)[i*2]   = __floats2half2_rn(v.x, v.y);
        ((__half2*)xh)[i*2+1] = __floats2half2_rn(v.z, v.w);
    } else if (i < N_X4 + N_W14) {
        int j = i - N_X4;
        split_one(((const float4*)w1)[j], w1hi, w1lo, j);
    } else if (i < N_X4 + N_W14 + N_W24) {
        int j = i - N_X4 - N_W14;
        split_one(((const float4*)w2)[j], w2hi, w2lo, j);
    } else if (i < N_PREP) {
        int j = i - N_X4 - N_W14 - N_W24;
        float4 v = (j < N_WXR) ? ((const float4*)wx)[j]
                               : make_float4(0.f, 0.f, 0.f, 0.f);
        split_one(v, wxhi, wxlo, j);
    }
}

// =====================================================================
// Tensor-core GEMM, fp16 2-term (proven R7/R8 config, unchanged).
// =====================================================================
#define GLDA 40
#define ARR_B  (128*GLDA*2)
#define STAGE_B (3*ARR_B)
#define NSTAGE 3
#define GEMM_SMEM (NSTAGE*STAGE_B)

__device__ __forceinline__ void mma16816h(float* c, const uint32_t* a, const uint32_t* b) {
    asm volatile(
        "mma.sync.aligned.m16n8k16.row.col.f32.f16.f16.f32 "
        "{%0,%1,%2,%3}, {%4,%5,%6,%7}, {%8,%9}, {%0,%1,%2,%3};"
        : "+f"(c[0]), "+f"(c[1]), "+f"(c[2]), "+f"(c[3])
        : "r"(a[0]), "r"(a[1]), "r"(a[2]), "r"(a[3]), "r"(b[0]), "r"(b[1]));
}
__device__ __forceinline__ void ldm4(uint32_t* r, uint32_t addr) {
    asm volatile(
        "ldmatrix.sync.aligned.m8n8.x4.shared.b16 {%0,%1,%2,%3}, [%4];"
        : "=r"(r[0]), "=r"(r[1]), "=r"(r[2]), "=r"(r[3]) : "r"(addr));
}
__device__ __forceinline__ void cpasync16(uint32_t dst, const void* src) {
    asm volatile("cp.async.cg.shared.global [%0], [%1], 16;" :: "r"(dst), "l"(src));
}

__global__ __launch_bounds__(256, 2) void gemm_fp16_2t(
    const __half* __restrict__ A,
    const __half* __restrict__ Whi, const __half* __restrict__ Wlo,
    float* __restrict__ C, int M, int N, int K)
{
    extern __shared__ __align__(16) char dsm[];

    const int tid  = threadIdx.x;
    const int lane = tid & 31;
    const int warp = tid >> 5;
    const int wm   = warp >> 2;
    const int wn   = warp & 3;
    const int brow = blockIdx.y * 128;
    const int bcol = blockIdx.x * 128;

    float acc[4][4][4];
    #pragma unroll
    for (int i = 0; i < 4; i++)
        #pragma unroll
        for (int j = 0; j < 4; j++)
            #pragma unroll
            for (int k = 0; k < 4; k++) acc[i][j][k] = 0.f;

    const uint32_t sbase = (uint32_t)__cvta_generic_to_shared(dsm);

    const __half* srcs[3];
    srcs[0] = A   + (size_t)(brow) * K;
    srcs[1] = Whi + (size_t)(bcol) * K;
    srcs[2] = Wlo + (size_t)(bcol) * K;

    uint32_t offA[4];
    #pragma unroll
    for (int mi = 0; mi < 4; mi++) {
        int row = wm * 64 + mi * 16 + (lane & 15);
        int ko  = (lane >> 4) * 8;
        offA[mi] = (uint32_t)(row * GLDA + ko) * 2u;
    }
    uint32_t offB[2];
    #pragma unroll
    for (int ni2 = 0; ni2 < 2; ni2++) {
        int row = wn * 32 + ni2 * 16 + (lane & 7) + ((lane >> 4) << 3);
        int ko  = ((lane >> 3) & 1) * 8;
        offB[ni2] = (uint32_t)(row * GLDA + ko) * 2u;
    }

    const int NK = K / 32;

    auto load_slab = [&](int slab, int stage) {
        const uint32_t stB = sbase + (uint32_t)stage * STAGE_B;
        #pragma unroll
        for (int arr = 0; arr < 3; arr++) {
            const __half* sp = srcs[arr] + slab * 32;
            #pragma unroll
            for (int j = 0; j < 2; j++) {
                int idx = tid + j * 256;
                int row = idx >> 2;
                int kc  = idx & 3;
                uint32_t dst = stB + (uint32_t)arr * ARR_B + (uint32_t)(row * GLDA + kc * 8) * 2u;
                cpasync16(dst, sp + (size_t)row * K + kc * 8);
            }
        }
        asm volatile("cp.async.commit_group;");
    };

    load_slab(0, 0);
    load_slab(1, 1);

    for (int kt = 0; kt < NK; kt++) {
        const int stage = kt % 3;
        if (kt < NK - 1) asm volatile("cp.async.wait_group 1;");
        else             asm volatile("cp.async.wait_group 0;");
        __syncthreads();

        if (kt + 2 < NK) load_slab(kt + 2, (kt + 2) % 3);

        const uint32_t stA   = sbase + (uint32_t)stage * STAGE_B;
        const uint32_t stWhi = stA + ARR_B;
        const uint32_t stWlo = stA + 2 * ARR_B;

        #pragma unroll
        for (int ks = 0; ks < 2; ks++) {
            const uint32_t kadd = (uint32_t)(ks * 32);
            uint32_t a[4][4], bhi[2][4], blo[2][4];
            #pragma unroll
            for (int ni2 = 0; ni2 < 2; ni2++) {
                ldm4(bhi[ni2], stWhi + offB[ni2] + kadd);
                ldm4(blo[ni2], stWlo + offB[ni2] + kadd);
            }
            #pragma unroll
            for (int mi = 0; mi < 4; mi++)
                ldm4(a[mi], stA + offA[mi] + kadd);
            #pragma unroll
            for (int mi = 0; mi < 4; mi++) {
                #pragma unroll
                for (int nf = 0; nf < 4; nf++) {
                    const int ni2 = nf >> 1;
                    const int s   = (nf & 1) * 2;
                    uint32_t bh[2] = { bhi[ni2][s], bhi[ni2][s + 1] };
                    uint32_t bl[2] = { blo[ni2][s], blo[ni2][s + 1] };
                    mma16816h(acc[mi][nf], a[mi], bh);
                    mma16816h(acc[mi][nf], a[mi], bl);
                }
            }
        }
    }

    const int gid = lane >> 2;
    const int tig = lane & 3;
    #pragma unroll
    for (int mi = 0; mi < 4; mi++) {
        #pragma unroll
        for (int nf = 0; nf < 4; nf++) {
            int row = brow + wm * 64 + mi * 16 + gid;
            int col = bcol + wn * 32 + nf * 8 + tig * 2;
            *(float2*)(C + (size_t)row * N + col) =
                make_float2(acc[mi][nf][0], acc[mi][nf][1]);
            *(float2*)(C + (size_t)(row + 8) * N + col) =
                make_float2(acc[mi][nf][2], acc[mi][nf][3]);
        }
    }
}

// =====================================================================
// Depthwise causal conv (width 4) + bias + SiLU; emits ONLY fp16 hi/lo
// (scans reconstruct x = hi + lo; xproj consumes hi/lo directly).
// =====================================================================
__global__ void conv_silu_kernel(const float* __restrict__ xz,
                                 const float* __restrict__ cw,
                                 const float* __restrict__ cb,
                                 __half* __restrict__ xchi,
                                 __half* __restrict__ xclo)
{
    int idx = blockIdx.x * blockDim.x + threadIdx.x;
    if (idx >= MROWS * DD / 4) return;
    int d4 = idx & (DD / 4 - 1);
    int bt = idx >> 8;
    int t  = bt & (TT - 1);
    int b  = bt >> 11;

    float4 cw0 = ((const float4*)cw)[d4 * 4 + 0];
    float4 cw1 = ((const float4*)cw)[d4 * 4 + 1];
    float4 cw2 = ((const float4*)cw)[d4 * 4 + 2];
    float4 cw3 = ((const float4*)cw)[d4 * 4 + 3];
    float4 acc = ((const float4*)cb)[d4];

    #pragma unroll
    for (int j = 0; j < DCONV; j++) {
        int tt = t - (DCONV - 1) + j;
        if (tt >= 0) {
            float4 xv = *(const float4*)(xz + (size_t)(b * TT + tt) * E2 + d4 * 4);
            float w0 = (&cw0.x)[j], w1 = (&cw1.x)[j], w2 = (&cw2.x)[j], w3 = (&cw3.x)[j];
            acc.x = fmaf(xv.x, w0, acc.x);
            acc.y = fmaf(xv.y, w1, acc.y);
            acc.z = fmaf(xv.z, w2, acc.z);
            acc.w = fmaf(xv.w, w3, acc.w);
        }
    }
    acc.x = acc.x / (1.0f + __expf(-acc.x));
    acc.y = acc.y / (1.0f + __expf(-acc.y));
    acc.z = acc.z / (1.0f + __expf(-acc.z));
    acc.w = acc.w / (1.0f + __expf(-acc.w));
    split_one(acc, xchi, xclo, idx);
}

// reconstruct conv output (hi+lo) at element index
__device__ __forceinline__ float xrec(const __half* hi, const __half* lo, size_t i) {
    return __half2float(hi[i]) + __half2float(lo[i]);
}

// =====================================================================
// Tensor-core x_proj (3-term fp16), K-split — unchanged from R15.
// =====================================================================
#define XA_B (128*GLDA*2)
#define XW_B (64*GLDA*2)
#define XSTAGE_B (2*XA_B + 2*XW_B)
#define XPROJ_SMEM (2*XSTAGE_B)

__global__ __launch_bounds__(256, 2) void xproj_mma(
    const __half* __restrict__ Ahi, const __half* __restrict__ Alo,
    const __half* __restrict__ Whi, const __half* __restrict__ Wlo,
    float* __restrict__ pp)
{
    extern __shared__ __align__(16) char dsm[];

    const int tid  = threadIdx.x;
    const int lane = tid & 31;
    const int warp = tid >> 5;
    const int wm   = warp >> 2;
    const int wn   = warp & 3;
    const int brow = blockIdx.x * 128;
    const int kbase = blockIdx.y * KCH;

    float acc[4][2][4];
    #pragma unroll
    for (int i = 0; i < 4; i++)
        #pragma unroll
        for (int j = 0; j < 2; j++)
            #pragma unroll
            for (int k = 0; k < 4; k++) acc[i][j][k] = 0.f;

    const uint32_t sbase = (uint32_t)__cvta_generic_to_shared(dsm);

    const __half* aSrc[2] = { Ahi + (size_t)brow * DD + kbase,
                              Alo + (size_t)brow * DD + kbase };
    const __half* wSrc[2] = { Whi + kbase, Wlo + kbase };

    uint32_t offA[4];
    #pragma unroll
    for (int mi = 0; mi < 4; mi++) {
        int row = wm * 64 + mi * 16 + (lane & 15);
        int ko  = (lane >> 4) * 8;
        offA[mi] = (uint32_t)(row * GLDA + ko) * 2u;
    }
    uint32_t offB;
    {
        int row = wn * 16 + (lane & 7) + ((lane >> 4) << 3);
        int ko  = ((lane >> 3) & 1) * 8;
        offB = (uint32_t)(row * GLDA + ko) * 2u;
    }

    const int NK = KCH / 32;

    auto load_slab = [&](int slab, int stage) {
        const uint32_t stB = sbase + (uint32_t)stage * XSTAGE_B;
        #pragma unroll
        for (int arr = 0; arr < 2; arr++) {
            const __half* sp = aSrc[arr] + slab * 32;
            #pragma unroll
            for (int j = 0; j < 2; j++) {
                int idx = tid * 2 + j;
                int row = idx >> 2;
                int kc  = idx & 3;
                uint32_t dst = stB + (uint32_t)arr * XA_B + (uint32_t)(row * GLDA + kc * 8) * 2u;
                cpasync16(dst, sp + (size_t)row * DD + kc * 8);
            }
        }
        #pragma unroll
        for (int arr = 0; arr < 2; arr++) {
            const __half* sp = wSrc[arr] + slab * 32;
            int row = tid >> 2;
            int kc  = tid & 3;
            uint32_t dst = stB + 2u * XA_B + (uint32_t)arr * XW_B + (uint32_t)(row * GLDA + kc * 8) * 2u;
            cpasync16(dst, sp + (size_t)row * DD + kc * 8);
        }
        asm volatile("cp.async.commit_group;");
    };

    load_slab(0, 0);
    load_slab(1, 1);

    for (int kt = 0; kt < NK; kt++) {
        const int stage = kt & 1;
        if (kt < NK - 1) asm volatile("cp.async.wait_group 1;");
        else             asm volatile("cp.async.wait_group 0;");
        __syncthreads();

        const uint32_t stAhi = sbase + (uint32_t)stage * XSTAGE_B;
        const uint32_t stAlo = stAhi + XA_B;
        const uint32_t stWhi = stAhi + 2 * XA_B;
        const uint32_t stWlo = stWhi + XW_B;

        #pragma unroll
        for (int ks = 0; ks < 2; ks++) {
            const uint32_t kadd = (uint32_t)(ks * 32);
            uint32_t ahi[4][4], alo[4][4], bhi[4], blo[4];
            ldm4(bhi, stWhi + offB + kadd);
            ldm4(blo, stWlo + offB + kadd);
            #pragma unroll
            for (int mi = 0; mi < 4; mi++) {
                ldm4(ahi[mi], stAhi + offA[mi] + kadd);
                ldm4(alo[mi], stAlo + offA[mi] + kadd);
            }
            #pragma unroll
            for (int mi = 0; mi < 4; mi++) {
                #pragma unroll
                for (int nf = 0; nf < 2; nf++) {
                    uint32_t bh[2] = { bhi[nf * 2], bhi[nf * 2 + 1] };
                    uint32_t bl[2] = { blo[nf * 2], blo[nf * 2 + 1] };
                    mma16816h(acc[mi][nf], ahi[mi], bh);
                    mma16816h(acc[mi][nf], alo[mi], bh);
                    mma16816h(acc[mi][nf], ahi[mi], bl);
                }
            }
        }
        if (kt + 2 < NK) load_slab(kt + 2, stage);
    }

    float* base = pp + (size_t)blockIdx.y * MROWS * NPAR;
    const int gid = lane >> 2;
    const int tig = lane & 3;
    #pragma unroll
    for (int mi = 0; mi < 4; mi++) {
        #pragma unroll
        for (int nf = 0; nf < 2; nf++) {
            int row = brow + wm * 64 + mi * 16 + gid;
            int e   = wn * 16 + nf * 8 + tig * 2;
            if (e < NPAR) {
                float* r0 = base + (size_t)row * NPAR + e;
                float* r1 = base + (size_t)(row + 8) * NPAR + e;
                r0[0] = acc[mi][nf][0];
                r1[0] = acc[mi][nf][2];
                if (e + 1 < NPAR) {
                    r0[1] = acc[mi][nf][1];
                    r1[1] = acc[mi][nf][3];
                }
            }
        }
    }
}

// =====================================================================
// Scan pass A: local chunk scan; stores P, hend.
// =====================================================================
#define SPQ (CHL*NPAR/4)
#define PSTR ((size_t)MROWS*NPAR/4)

__global__ __launch_bounds__(128) void scanA_kernel(const float* __restrict__ params,
                                                    const __half* __restrict__ xchi,
                                                    const __half* __restrict__ xclo,
                                                    const float* __restrict__ dtw,
                                                    const float* __restrict__ dtb,
                                                    const float* __restrict__ A_log,
                                                    float* __restrict__ Pout,
                                                    float* __restrict__ hend)
{
    __shared__ float sp[CHL][36];
    const int dg = blockIdx.x & 7;
    const int c  = (blockIdx.x >> 3) & (NCH - 1);
    const int b  = blockIdx.x >> 8;
    const int d  = dg * 128 + threadIdx.x;
    const size_t rowbase = (size_t)b * TT + (size_t)c * CHL;

    {
        const float4* src = (const float4*)(params + rowbase * NPAR);
        for (int i = threadIdx.x; i < SPQ; i += 128) {
            float4 v0 = src[i];
            float4 v1 = src[i + PSTR];
            float4 v2 = src[i + 2 * PSTR];
            float4 v3 = src[i + 3 * PSTR];
            float4 v = make_float4((v0.x + v1.x) + (v2.x + v3.x),
                                   (v0.y + v1.y) + (v2.y + v3.y),
                                   (v0.z + v1.z) + (v2.z + v3.z),
                                   (v0.w + v1.w) + (v2.w + v3.w));
            int e = i * 4;
            #pragma unroll
            for (int j = 0; j < 4; j++) {
                int ee = e + j;
                sp[ee / NPAR][ee % NPAR] = (&v.x)[j];
            }
        }
    }

    float a[NN];
    #pragma unroll
    for (int n = 0; n < NN; n++)
        a[n] = -expf(A_log[(size_t)d * NN + n]);
    const float w    = dtw[d];
    const float bias = dtb[d];

    bool fast = true;
    #pragma unroll
    for (int n = 1; n < NN; n++)
        fast = fast && (fabsf(a[n] - (float)(n + 1) * a[0]) <= 1e-4f * fabsf(a[n]) + 1e-12f);

    float h[NN], P[NN];
    #pragma unroll
    for (int n = 0; n < NN; n++) { h[n] = 0.f; P[n] = 1.f; }

    __syncthreads();

    if (fast) {
        const float a0 = a[0];
        for (int t = 0; t < CHL; t++) {
            float pv[16];
            *(float4*)&pv[0]  = *(const float4*)&sp[t][0];
            *(float4*)&pv[4]  = *(const float4*)&sp[t][4];
            *(float4*)&pv[8]  = *(const float4*)&sp[t][8];
            *(float4*)&pv[12] = *(const float4*)&sp[t][12];
            float v  = fmaf(sp[t][32], w, bias);
            float dt = (v > 20.f) ? v : __logf(1.0f + __expf(v));
            float dtx = dt * xrec(xchi, xclo, (rowbase + t) * DD + d);
            float q = __expf(dt * a0);
            float e = q;
            #pragma unroll
            for (int n = 0; n < NN; n++) {
                h[n] = fmaf(e, h[n], dtx * pv[n]);
                P[n] *= e;
                e *= q;
            }
        }
    } else {
        for (int t = 0; t < CHL; t++) {
            float pv[16];
            *(float4*)&pv[0]  = *(const float4*)&sp[t][0];
            *(float4*)&pv[4]  = *(const float4*)&sp[t][4];
            *(float4*)&pv[8]  = *(const float4*)&sp[t][8];
            *(float4*)&pv[12] = *(const float4*)&sp[t][12];
            float v  = fmaf(sp[t][32], w, bias);
            float dt = (v > 20.f) ? v : __logf(1.0f + __expf(v));
            float dtx = dt * xrec(xchi, xclo, (rowbase + t) * DD + d);
            #pragma unroll
            for (int n = 0; n < NN; n++) {
                float e = __expf(dt * a[n]);
                h[n] = fmaf(e, h[n], dtx * pv[n]);
                P[n] *= e;
            }
        }
    }
    const size_t o = ((size_t)(b * NCH + c) * NN) * DD + d;
    #pragma unroll
    for (int n = 0; n < NN; n++) {
        hend[o + (size_t)n * DD] = h[n];
        Pout[o + (size_t)n * DD] = P[n];
    }
}

// =====================================================================
// Scan pass C (scanB folded in): each block folds its prefix chunks
// (P/hend from L2) to get h_init, then re-runs its chunk emitting y.
// =====================================================================
__global__ __launch_bounds__(128) void scanC_kernel(const float* __restrict__ params,
                                                    const __half* __restrict__ xchi,
                                                    const __half* __restrict__ xclo,
                                                    const float* __restrict__ xz,
                                                    const float* __restrict__ dtw,
                                                    const float* __restrict__ dtb,
                                                    const float* __restrict__ A_log,
                                                    const float* __restrict__ Pg,
                                                    const float* __restrict__ hend,
                                                    __half* __restrict__ yh)
{
    __shared__ float sp[CHL][36];
    const int dg = blockIdx.x & 7;
    const int c  = (blockIdx.x >> 3) & (NCH - 1);
    const int b  = blockIdx.x >> 8;
    const int d  = dg * 128 + threadIdx.x;
    const size_t rowbase = (size_t)b * TT + (size_t)c * CHL;

    {
        const float4* src = (const float4*)(params + rowbase * NPAR);
        for (int i = threadIdx.x; i < SPQ; i += 128) {
            float4 v0 = src[i];
            float4 v1 = src[i + PSTR];
            float4 v2 = src[i + 2 * PSTR];
            float4 v3 = src[i + 3 * PSTR];
            float4 v = make_float4((v0.x + v1.x) + (v2.x + v3.x),
                                   (v0.y + v1.y) + (v2.y + v3.y),
                                   (v0.z + v1.z) + (v2.z + v3.z),
                                   (v0.w + v1.w) + (v2.w + v3.w));
            int e = i * 4;
            #pragma unroll
            for (int j = 0; j < 4; j++) {
                int ee = e + j;
                sp[ee / NPAR][ee % NPAR] = (&v.x)[j];
            }
        }
    }

    float a[NN];
    #pragma unroll
    for (int n = 0; n < NN; n++)
        a[n] = -expf(A_log[(size_t)d * NN + n]);
    const float w    = dtw[d];
    const float bias = dtb[d];

    bool fast = true;
    #pragma unroll
    for (int n = 1; n < NN; n++)
        fast = fast && (fabsf(a[n] - (float)(n + 1) * a[0]) <= 1e-4f * fabsf(a[n]) + 1e-12f);

    // fold prefix chunks 0..c-1 -> h_init (same order as old scanB)
    float h[NN];
    #pragma unroll
    for (int n = 0; n < NN; n++) h[n] = 0.f;
    for (int cc = 0; cc < c; cc++) {
        const size_t oc = ((size_t)(b * NCH + cc) * NN) * DD + d;
        #pragma unroll
        for (int n = 0; n < NN; n++)
            h[n] = fmaf(Pg[oc + (size_t)n * DD], h[n], hend[oc + (size_t)n * DD]);
    }

    __syncthreads();

    if (fast) {
        const float a0 = a[0];
        for (int t = 0; t < CHL; t++) {
            const size_t r = rowbase + t;
            float pv[16], cv[16];
            *(float4*)&pv[0]  = *(const float4*)&sp[t][0];
            *(float4*)&pv[4]  = *(const float4*)&sp[t][4];
            *(float4*)&pv[8]  = *(const float4*)&sp[t][8];
            *(float4*)&pv[12] = *(const float4*)&sp[t][12];
            *(float4*)&cv[0]  = *(const float4*)&sp[t][16];
            *(float4*)&cv[4]  = *(const float4*)&sp[t][20];
            *(float4*)&cv[8]  = *(const float4*)&sp[t][24];
            *(float4*)&cv[12] = *(const float4*)&sp[t][28];
            float v  = fmaf(sp[t][32], w, bias);
            float dt = (v > 20.f) ? v : __logf(1.0f + __expf(v));
            float dtx = dt * xrec(xchi, xclo, r * DD + d);
            float zv  = xz[r * E2 + DD + d];
            float q = __expf(dt * a0);
            float e = q;
            float yv = 0.f;
            #pragma unroll
            for (int n = 0; n < NN; n++) {
                h[n] = fmaf(e, h[n], dtx * pv[n]);
                yv = fmaf(h[n], cv[n], yv);
                e *= q;
            }
            float sil = zv / (1.0f + __expf(-zv));
            yh[r * DD + d] = __float2half_rn(yv * sil);
        }
    } else {
        for (int t = 0; t < CHL; t++) {
            const size_t r = rowbase + t;
            float pv[16], cv[16];
            *(float4*)&pv[0]  = *(const float4*)&sp[t][0];
            *(float4*)&pv[4]  = *(const float4*)&sp[t][4];
            *(float4*)&pv[8]  = *(const float4*)&sp[t][8];
            *(float4*)&pv[12] = *(const float4*)&sp[t][12];
            *(float4*)&cv[0]  = *(const float4*)&sp[t][16];
            *(float4*)&cv[4]  = *(const float4*)&sp[t][20];
            *(float4*)&cv[8]  = *(const float4*)&sp[t][24];
            *(float4*)&cv[12] = *(const float4*)&sp[t][28];
            float v  = fmaf(sp[t][32], w, bias);
            float dt = (v > 20.f) ? v : __logf(1.0f + __expf(v));
            float dtx = dt * xrec(xchi, xclo, r * DD + d);
            float zv  = xz[r * E2 + DD + d];
            float yv = 0.f;
            #pragma unroll
            for (int n = 0; n < NN; n++) {
                float e = __expf(dt * a[n]);
                h[n] = fmaf(e, h[n], dtx * pv[n]);
                yv = fmaf(h[n], cv[n], yv);
            }
            float sil = zv / (1.0f + __expf(-zv));
            yh[r * DD + d] = __float2half_rn(yv * sil);
        }
    }
}

// =====================================================================
// launch
// =====================================================================
extern "C" void kernel_launch(void* const* d_in, const int* in_sizes, int n_in,
                              void* d_out, int out_size)
{
    const float* x         = (const float*)d_in[0];
    const float* in_proj_w = (const float*)d_in[1];
    const float* conv_w    = (const float*)d_in[2];
    const float* conv_b    = (const float*)d_in[3];
    const float* x_proj_w  = (const float*)d_in[4];
    const float* dt_proj_w = (const float*)d_in[5];
    const float* dt_proj_b = (const float*)d_in[6];
    const float* A_log     = (const float*)d_in[7];
    const float* out_proj_w= (const float*)d_in[8];
    float* out = (float*)d_out;

    float *xz, *params, *P, *hend;
    __half *xh, *w1hi, *w1lo, *w2hi, *w2lo, *yh, *xchi, *xclo, *wxhi, *wxlo;
    cudaGetSymbolAddress((void**)&xz,     g_xz);
    cudaGetSymbolAddress((void**)&params, g_params);
    cudaGetSymbolAddress((void**)&P,      g_P);
    cudaGetSymbolAddress((void**)&hend,   g_hend);
    cudaGetSymbolAddress((void**)&xh,     g_xh);
    cudaGetSymbolAddress((void**)&w1hi,   g_w1hi);
    cudaGetSymbolAddress((void**)&w1lo,   g_w1lo);
    cudaGetSymbolAddress((void**)&w2hi,   g_w2hi);
    cudaGetSymbolAddress((void**)&w2lo,   g_w2lo);
    cudaGetSymbolAddress((void**)&yh,     g_yh);
    cudaGetSymbolAddress((void**)&xchi,   g_xchi);
    cudaGetSymbolAddress((void**)&xclo,   g_xclo);
    cudaGetSymbolAddress((void**)&wxhi,   g_wxhi);
    cudaGetSymbolAddress((void**)&wxlo,   g_wxlo);

    cudaFuncSetAttribute(gemm_fp16_2t,
                         cudaFuncAttributeMaxDynamicSharedMemorySize, GEMM_SMEM);
    cudaFuncSetAttribute(xproj_mma,
                         cudaFuncAttributeMaxDynamicSharedMemorySize, XPROJ_SMEM);

    // 0) merged precision prep
    prep_kernel<<<(N_PREP + 255)/256, 256>>>(x, in_proj_w, out_proj_w, x_proj_w,
                                             xh, w1hi, w1lo, w2hi, w2lo, wxhi, wxlo);

    // 1) in_proj
    {
        dim3 grid(E2 / 128, MROWS / 128);
        gemm_fp16_2t<<<grid, 256, GEMM_SMEM>>>(xh, w1hi, w1lo, xz, MROWS, E2, DD);
    }
    // 2) depthwise conv + SiLU (fp16 hi/lo only)
    conv_silu_kernel<<<(MROWS*DD/4 + 255)/256, 256>>>(xz, conv_w, conv_b, xchi, xclo);
    // 3) x_proj (tensor-core, 3-term, K-split)
    {
        dim3 grid(MROWS / 128, KSPL);
        xproj_mma<<<grid, 256, XPROJ_SMEM>>>(xchi, xclo, wxhi, wxlo, params);
    }
    // 4) chunked selective scan (pass B folded into pass C)
    scanA_kernel<<<BB * NCH * (DD/128), 128>>>(params, xchi, xclo, dt_proj_w, dt_proj_b, A_log, P, hend);
    scanC_kernel<<<BB * NCH * (DD/128), 128>>>(params, xchi, xclo, xz, dt_proj_w, dt_proj_b, A_log, P, hend, yh);
    // 5) out_proj
    {
        dim3 grid(DD / 128, MROWS / 128);
        gemm_fp16_2t<<<grid, 256, GEMM_SMEM>>>(yh, w2hi, w2lo, out, MROWS, DD, DD);
    }
}